// round 15
// baseline (speedup 1.0000x reference)
#include <cuda_runtime.h>
#include <cuda_fp16.h>
#include <cstdint>

#define BB 16
#define NN 2048
#define SS 2048
#define DD 256

#define KQK 256       // hi-only fp16 GEMM depth
#define BM 128
#define BN 128
#define BKH 64        // K-chunk in halves
#define LDSH 72       // smem row stride in halves (+8 pad)

#define NTILE (SS / BN)   // 16 column tiles per row
#define NSLOT 8           // candidate slots per (row, tile)
#define MARGIN 0.1f       // fp16 approx-score safety margin (~12 sigma)

// Static device scratch (allocation-free, fully rewritten each run)
__device__ float  d_cval[(size_t)BB * NN * NTILE * NSLOT];
__device__ int    d_cidx[(size_t)BB * NN * NTILE * NSLOT];
__device__ int    d_ccnt[(size_t)BB * NN * NTILE];
__device__ __half d_qc[(size_t)BB * NN * KQK];
__device__ __half d_kc[(size_t)BB * SS * KQK];
__device__ int    d_done[BB * (NN / BM)];   // completion counters (self-resetting)

__device__ __forceinline__ uint32_t smem_u32(const void* p) {
    uint32_t a;
    asm("{ .reg .u64 t; cvta.to.shared.u64 t, %1; cvt.u32.u64 %0, t; }"
        : "=r"(a) : "l"(p));
    return a;
}

__device__ __forceinline__ void cp16(uint32_t dst, const void* src) {
    asm volatile("cp.async.cg.shared.global [%0], [%1], 16;" :: "r"(dst), "l"(src));
}

// Streaming (evict-first) zero store: keeps fill traffic out of hot L2 sets.
__device__ __forceinline__ void stg_cs_zero16(float* p) {
    asm volatile("st.global.cs.v4.f32 [%0], {%1, %1, %1, %1};"
                 :: "l"(p), "f"(0.0f) : "memory");
}

// ---------------------------------------------------------------------------
// Pre-convert: d_qc/d_kc = fp16(Q), fp16(K)  (hi parts only)
// ---------------------------------------------------------------------------
__global__ __launch_bounds__(256) void convert_kernel(
    const float* __restrict__ Q, const float* __restrict__ K)
{
    const size_t v = (size_t)blockIdx.x * 256 + threadIdx.x; // < BB*NN*DD/4
    const size_t row = v >> 6;
    const int d = (int)(v & 63) * 4;

    float4 q = *(const float4*)(Q + row * DD + d);
    float4 k = *(const float4*)(K + row * DD + d);

    __half qh[4] = {__float2half_rn(q.x), __float2half_rn(q.y),
                    __float2half_rn(q.z), __float2half_rn(q.w)};
    __half kh[4] = {__float2half_rn(k.x), __float2half_rn(k.y),
                    __float2half_rn(k.z), __float2half_rn(k.w)};
    *(uint2*)(d_qc + row * KQK + d) = *(uint2*)qh;
    *(uint2*)(d_kc + row * KQK + d) = *(uint2*)kh;
}

// ---------------------------------------------------------------------------
// Per-row finisher (warp-collective): merge candidate lists, exact fp32
// rescore, sparsemax, V gather, gate scatter. cvp/cip: this warp's smem.
// ---------------------------------------------------------------------------
__device__ __forceinline__ void finish_row(
    int b, int row_g, const float* __restrict__ Q, const float* __restrict__ Kk,
    float* __restrict__ G, float* __restrict__ A,
    float* __restrict__ Vout, const float* __restrict__ Vals,
    float* cvp, int* cip, int lane)
{
    // Lanes 0..15 each own one tile's candidate list
    int cnt = 0;
    float tv[NSLOT];
    int   tix[NSLOT];
    if (lane < NTILE) {
        cnt = d_ccnt[(size_t)row_g * NTILE + lane];
        const size_t base = ((size_t)row_g * NTILE + lane) * NSLOT;
#pragma unroll
        for (int s = 0; s < NSLOT; ++s) {
            if (s < cnt) { tv[s] = d_cval[base + s]; tix[s] = d_cidx[base + s]; }
        }
    }

    // Approx global row max
    float m = -1e30f;
#pragma unroll
    for (int s = 0; s < NSLOT; ++s)
        if (s < cnt) m = fmaxf(m, tv[s]);
#pragma unroll
    for (int o = 16; o > 0; o >>= 1) m = fmaxf(m, __shfl_xor_sync(0xffffffffu, m, o));
    const float thr = m - 1.0f - MARGIN;

    // Compact survivors into shared list
    int base = 0;
#pragma unroll
    for (int s = 0; s < NSLOT; ++s) {
        bool p = (s < cnt) && (tv[s] > thr);
        unsigned msk = __ballot_sync(0xffffffffu, p);
        if (p) {
            int pos = base + __popc(msk & ((1u << lane) - 1u));
            if (pos < 32) cip[pos] = tix[s];
        }
        base += __popc(msk);
    }
    const int mc = base > 32 ? 32 : base;
    __syncwarp();

    // Exact fp32 rescoring: warp-cooperative dot products
    const float* Qr = Q + (size_t)row_g * DD;
    float4 q0 = ((const float4*)Qr)[lane * 2];
    float4 q1 = ((const float4*)Qr)[lane * 2 + 1];
    for (int i = 0; i < mc; ++i) {
        const float* Kr = Kk + ((size_t)b * SS + cip[i]) * DD;
        float4 k0 = ((const float4*)Kr)[lane * 2];
        float4 k1 = ((const float4*)Kr)[lane * 2 + 1];
        float p = q0.x * k0.x + q0.y * k0.y + q0.z * k0.z + q0.w * k0.w
                + q1.x * k1.x + q1.y * k1.y + q1.z * k1.z + q1.w * k1.w;
#pragma unroll
        for (int o = 16; o > 0; o >>= 1) p += __shfl_xor_sync(0xffffffffu, p, o);
        cvp[i] = p;
    }
    __syncwarp();

    // Sparsemax on exact candidate scores
    float cand = (lane < mc) ? cvp[lane] : -1e30f;
    float me = cand;
#pragma unroll
    for (int o = 16; o > 0; o >>= 1) me = fmaxf(me, __shfl_xor_sync(0xffffffffu, me, o));
    float lo = me - 1.0f, hi = me;
    for (int it = 0; it < 20; ++it) {
        float mid = 0.5f * (lo + hi);
        float s = fmaxf(cand - mid, 0.0f);
#pragma unroll
        for (int o = 16; o > 0; o >>= 1) s += __shfl_xor_sync(0xffffffffu, s, o);
        if (s >= 1.0f) lo = mid; else hi = mid;
    }
    float inz = (cand > lo) ? cand : 0.0f;
    float inc = (cand > lo) ? 1.0f : 0.0f;
#pragma unroll
    for (int o = 16; o > 0; o >>= 1) {
        inz += __shfl_xor_sync(0xffffffffu, inz, o);
        inc += __shfl_xor_sync(0xffffffffu, inc, o);
    }
    const float tau = (inz - 1.0f) / inc;
    const float g = fmaxf(cand - tau, 0.0f);

    // V[row,:] = sum_i g_i * Vals[b, s_i, :]
    float4 acc0 = make_float4(0.f, 0.f, 0.f, 0.f);
    float4 acc1 = make_float4(0.f, 0.f, 0.f, 0.f);
    for (int i = 0; i < mc; ++i) {
        float gi = __shfl_sync(0xffffffffu, g, i);
        if (gi > 0.0f) {
            const float4* vr = (const float4*)(Vals + ((size_t)b * SS + cip[i]) * DD + lane * 8);
            float4 p0 = vr[0], p1 = vr[1];
            acc0.x += gi * p0.x; acc0.y += gi * p0.y; acc0.z += gi * p0.z; acc0.w += gi * p0.w;
            acc1.x += gi * p1.x; acc1.y += gi * p1.y; acc1.z += gi * p1.z; acc1.w += gi * p1.w;
        }
    }
    float4* vo = (float4*)(Vout + (size_t)row_g * DD + lane * 8);
    vo[0] = acc0; vo[1] = acc1;

    // Scatter nonzero gates (zeros pre-written by the group's 16 CTAs)
    if (lane < mc && g > 0.0f) {
        int s = cip[lane];
        G[(size_t)row_g * SS + s] = g;
        A[(size_t)row_g * SS + s] = g;
    }
}

// ---------------------------------------------------------------------------
// Approx QK GEMM via HMMA (hi*hi) + interleaved streaming zero-fill +
// candidate extraction + last-CTA-per-row-group finisher (fused sparsemax).
// ---------------------------------------------------------------------------
__global__ void __launch_bounds__(256, 2) qk_hmma(
    const float* __restrict__ Q, const float* __restrict__ Kk,
    float* __restrict__ G, float* __restrict__ A,
    float* __restrict__ Vout, const float* __restrict__ Vals)
{
    extern __shared__ __align__(16) char smraw[];
    __half* As = (__half*)smraw;          // [2][BM][LDSH]
    __half* Bs = As + 2 * BM * LDSH;      // [2][BN][LDSH]

    const int tid = threadIdx.x, wid = tid >> 5, lane = tid & 31;
    const int warp_m = wid & 1;
    const int warp_n = wid >> 1;
    const int b = blockIdx.z;
    const int rowBase = blockIdx.y * BM;
    const int colBase = blockIdx.x * BN;
    const int tileX = blockIdx.x;
    const __half* Qb = d_qc + ((size_t)b * NN + rowBase) * KQK;
    const __half* Kb = d_kc + ((size_t)b * SS + colBase) * KQK;
    const uint32_t asb = smem_u32(As);
    const uint32_t bsb = smem_u32(Bs);

    float* Gt = G + ((size_t)b * NN + rowBase) * SS + colBase;
    float* At = A + ((size_t)b * NN + rowBase) * SS + colBase;

    float acc[4][4][4];
#pragma unroll
    for (int mt = 0; mt < 4; ++mt)
#pragma unroll
        for (int nt = 0; nt < 4; ++nt)
#pragma unroll
            for (int e = 0; e < 4; ++e) acc[mt][nt][e] = 0.0f;

#define ISSUE_STAGE(st, k0) do {                                              \
        _Pragma("unroll")                                                     \
        for (int l = 0; l < 4; ++l) {                                         \
            int idx = tid + l * 256;                                          \
            int row = idx >> 3;                                               \
            int c8  = (idx & 7) * 8;                                          \
            cp16(asb + (uint32_t)(((st) * BM * LDSH + row * LDSH + c8) * 2),  \
                 Qb + (size_t)row * KQK + (k0) + c8);                         \
            cp16(bsb + (uint32_t)(((st) * BN * LDSH + row * LDSH + c8) * 2),  \
                 Kb + (size_t)row * KQK + (k0) + c8);                         \
        }                                                                     \
        asm volatile("cp.async.commit_group;" ::: "memory");                  \
    } while (0)

    ISSUE_STAGE(0, 0);

    const int NK = KQK / BKH;   // 4
    for (int c = 0; c < NK; ++c) {
        if (c + 1 < NK) {
            ISSUE_STAGE((c + 1) & 1, (c + 1) * BKH);
            asm volatile("cp.async.wait_group 1;" ::: "memory");
        } else {
            asm volatile("cp.async.wait_group 0;" ::: "memory");
        }
        __syncthreads();

        // Interleaved zero-fill: 1/NK of this CTA's G/A tiles per chunk.
#pragma unroll
        for (int l = 0; l < 4; ++l) {
            int f = tid + (c * 4 + l) * 256;   // 0..4095 float4 positions
            int row = f >> 5;
            int c4 = (f & 31) * 4;
            stg_cs_zero16(Gt + (size_t)row * SS + c4);
            stg_cs_zero16(At + (size_t)row * SS + c4);
        }

        const int st = c & 1;
        const uint32_t ab = asb + (uint32_t)(st * BM * LDSH * 2);
        const uint32_t bbs = bsb + (uint32_t)(st * BN * LDSH * 2);

#pragma unroll
        for (int ks = 0; ks < BKH / 16; ++ks) {
            uint32_t a[4][4];
#pragma unroll
            for (int mt = 0; mt < 4; ++mt) {
                uint32_t addr = ab + (uint32_t)((((warp_m * 64 + mt * 16 + (lane & 15)) * LDSH)
                                 + ks * 16 + (lane >> 4) * 8) * 2);
                asm volatile(
                    "ldmatrix.sync.aligned.m8n8.x4.shared.b16 {%0,%1,%2,%3}, [%4];"
                    : "=r"(a[mt][0]), "=r"(a[mt][1]), "=r"(a[mt][2]), "=r"(a[mt][3])
                    : "r"(addr));
            }
            uint32_t bf[4][2];
#pragma unroll
            for (int g = 0; g < 2; ++g) {
                uint32_t addr = bbs + (uint32_t)((((warp_n * 32 + g * 16 + (lane & 15)) * LDSH)
                                 + ks * 16 + (lane >> 4) * 8) * 2);
                uint32_t r0, r1, r2, r3;
                asm volatile(
                    "ldmatrix.sync.aligned.m8n8.x4.shared.b16 {%0,%1,%2,%3}, [%4];"
                    : "=r"(r0), "=r"(r1), "=r"(r2), "=r"(r3)
                    : "r"(addr));
                bf[g * 2][0] = r0; bf[g * 2][1] = r2;
                bf[g * 2 + 1][0] = r1; bf[g * 2 + 1][1] = r3;
            }
#pragma unroll
            for (int mt = 0; mt < 4; ++mt)
#pragma unroll
                for (int nt = 0; nt < 4; ++nt) {
                    asm volatile(
                        "mma.sync.aligned.m16n8k16.row.col.f32.f16.f16.f32 "
                        "{%0,%1,%2,%3}, {%4,%5,%6,%7}, {%8,%9}, {%0,%1,%2,%3};"
                        : "+f"(acc[mt][nt][0]), "+f"(acc[mt][nt][1]),
                          "+f"(acc[mt][nt][2]), "+f"(acc[mt][nt][3])
                        : "r"(a[mt][0]), "r"(a[mt][1]), "r"(a[mt][2]), "r"(a[mt][3]),
                          "r"(bf[nt][0]), "r"(bf[nt][1]));
                }
        }
        __syncthreads();
    }
#undef ISSUE_STAGE

    // ---------------- Candidate-extraction epilogue --------------------
    float (*wmax)[4] = (float(*)[4])smraw;            // [128][4]
    float* tmax = (float*)(smraw + 2048);             // [128]
    int*   scnt = (int*)(smraw + 2560);               // [128]
    int*   lflag = (int*)(smraw + 3072);

#pragma unroll
    for (int mt = 0; mt < 4; ++mt) {
#pragma unroll
        for (int h = 0; h < 2; ++h) {
            float rm = -1e30f;
#pragma unroll
            for (int nt = 0; nt < 4; ++nt)
                rm = fmaxf(rm, fmaxf(acc[mt][nt][h * 2], acc[mt][nt][h * 2 + 1]));
            rm = fmaxf(rm, __shfl_xor_sync(0xffffffffu, rm, 1));
            rm = fmaxf(rm, __shfl_xor_sync(0xffffffffu, rm, 2));
            if ((lane & 3) == 0)
                wmax[warp_m * 64 + mt * 16 + h * 8 + (lane >> 2)][warp_n] = rm;
        }
    }
    __syncthreads();
    if (tid < 128) {
        float t = fmaxf(fmaxf(wmax[tid][0], wmax[tid][1]),
                        fmaxf(wmax[tid][2], wmax[tid][3]));
        tmax[tid] = t;
        scnt[tid] = 0;
    }
    __syncthreads();

#pragma unroll
    for (int mt = 0; mt < 4; ++mt) {
#pragma unroll
        for (int nt = 0; nt < 4; ++nt) {
#pragma unroll
            for (int e = 0; e < 4; ++e) {
                int r = warp_m * 64 + mt * 16 + ((e >> 1) ? 8 : 0) + (lane >> 2);
                float val = acc[mt][nt][e];
                if (val > tmax[r] - 1.0f - MARGIN) {
                    int pos = atomicAdd(&scnt[r], 1);
                    if (pos < NSLOT) {
                        size_t grow = (size_t)b * NN + rowBase + r;
                        size_t slot = (grow * NTILE + tileX) * NSLOT + pos;
                        d_cval[slot] = val;
                        d_cidx[slot] = colBase + warp_n * 32 + nt * 8
                                       + 2 * (lane & 3) + (e & 1);
                    }
                }
            }
        }
    }
    __syncthreads();
    if (tid < 128) {
        size_t grow = (size_t)b * NN + rowBase + tid;
        int cc = scnt[tid];
        d_ccnt[grow * NTILE + tileX] = cc < NSLOT ? cc : NSLOT;
    }
    __syncthreads();

    // ---------- Last-CTA-per-group finisher (threadFenceReduction) ------
    const int gidx = b * (NN / BM) + blockIdx.y;
    if (tid == 0) {
        __threadfence();   // release all fills + candidate writes
        int prev = atomicAdd(&d_done[gidx], 1);
        lflag[0] = (prev == NTILE - 1);
    }
    __syncthreads();
    if (!lflag[0]) return;

    if (tid == 0) d_done[gidx] = 0;   // reset for next graph replay
    __threadfence();                   // acquire peers' writes

    // Finisher: 8 warps x 16 rows each = 128 rows of this group.
    float* cvp = (float*)smraw + wid * 32;          // [8][32] floats
    int*   cip = (int*)(smraw + 1024) + wid * 32;   // [8][32] ints
    for (int it = 0; it < 16; ++it) {
        int row_g = b * NN + rowBase + it * 8 + wid;
        finish_row(b, row_g, Q, Kk, G, A, Vout, Vals, cvp, cip, lane);
    }
}

// ============================== launch =====================================
extern "C" void kernel_launch(void* const* d_in, const int* in_sizes, int n_in,
                              void* d_out, int out_size)
{
    const float* Q  = (const float*)d_in[0];
    const float* K  = (const float*)d_in[1];
    const float* Vv = (const float*)d_in[2];

    float* out  = (float*)d_out;
    float* Vout = out;
    float* Aout = out + (size_t)BB * NN * DD;
    float* Gout = Aout + (size_t)BB * NN * SS;

    const int QK_SMEM = 2 * (BM + BN) * LDSH * 2;     // 73,728 B
    cudaFuncSetAttribute(qk_hmma, cudaFuncAttributeMaxDynamicSharedMemorySize, QK_SMEM);

    // 1) convert Q,K to fp16 (hi only) into static scratch
    convert_kernel<<<(unsigned)((size_t)BB * NN * DD / 4 / 256), 256>>>(Q, K);

    // 2) fused: approx scores via HMMA -> candidates; zero-fill G/A;
    //    last CTA per row-group runs exact rescore + sparsemax + AV + scatter
    dim3 g1(SS / BN, NN / BM, BB);
    qk_hmma<<<g1, 256, QK_SMEM>>>(Q, K, Gout, Aout, Vout, Vv);
}

// round 16
// speedup vs baseline: 1.4593x; 1.4593x over previous
#include <cuda_runtime.h>
#include <cuda_fp16.h>
#include <cstdint>

#define BB 16
#define NN 2048
#define SS 2048
#define DD 256

#define KQK 256       // hi-only fp16 GEMM depth
#define BM 128
#define BN 128
#define BKH 64        // K-chunk in halves
#define LDSH 72       // smem row stride in halves (+8 pad)

#define NTILE (SS / BN)   // 16 column tiles per row
#define NSLOT 8           // candidate slots per (row, tile)
#define MARGIN 0.1f       // fp16 approx-score safety margin (~12 sigma)

// Static device scratch (allocation-free, fully rewritten each run)
__device__ float  d_cval[(size_t)BB * NN * NTILE * NSLOT];
__device__ int    d_cidx[(size_t)BB * NN * NTILE * NSLOT];
__device__ int    d_ccnt[(size_t)BB * NN * NTILE];
__device__ __half d_qc[(size_t)BB * NN * KQK];
__device__ __half d_kc[(size_t)BB * SS * KQK];

__device__ __forceinline__ uint32_t smem_u32(const void* p) {
    uint32_t a;
    asm("{ .reg .u64 t; cvta.to.shared.u64 t, %1; cvt.u32.u64 %0, t; }"
        : "=r"(a) : "l"(p));
    return a;
}

__device__ __forceinline__ void cp16(uint32_t dst, const void* src) {
    asm volatile("cp.async.cg.shared.global [%0], [%1], 16;" :: "r"(dst), "l"(src));
}

// Write-through zero store: writes past L2 without allocating lines,
// so fill traffic cannot evict the hot fp16 operand tiles.
__device__ __forceinline__ void stg_wt_zero16(float* p) {
    asm volatile("st.global.wt.v4.f32 [%0], {%1, %1, %1, %1};"
                 :: "l"(p), "f"(0.0f) : "memory");
}

// ---------------------------------------------------------------------------
// Pre-convert: d_qc/d_kc = fp16(Q), fp16(K)  (hi parts only)
// ---------------------------------------------------------------------------
__global__ __launch_bounds__(256) void convert_kernel(
    const float* __restrict__ Q, const float* __restrict__ K)
{
    const size_t v = (size_t)blockIdx.x * 256 + threadIdx.x; // < BB*NN*DD/4
    const size_t row = v >> 6;
    const int d = (int)(v & 63) * 4;

    float4 q = *(const float4*)(Q + row * DD + d);
    float4 k = *(const float4*)(K + row * DD + d);

    __half qh[4] = {__float2half_rn(q.x), __float2half_rn(q.y),
                    __float2half_rn(q.z), __float2half_rn(q.w)};
    __half kh[4] = {__float2half_rn(k.x), __float2half_rn(k.y),
                    __float2half_rn(k.z), __float2half_rn(k.w)};
    *(uint2*)(d_qc + row * KQK + d) = *(uint2*)qh;
    *(uint2*)(d_kc + row * KQK + d) = *(uint2*)kh;
}

// ---------------------------------------------------------------------------
// Approx QK GEMM via HMMA (hi*hi) + interleaved write-through zero-fill of
// the output gate tiles + candidate-extraction epilogue.
// CTA tile 128x128, 8 warps of 64x32, BK=64 halves, 2-stage cp.async.
// ---------------------------------------------------------------------------
__global__ void __launch_bounds__(256, 2) qk_hmma(
    float* __restrict__ G, float* __restrict__ A)
{
    extern __shared__ __align__(16) char smraw[];
    __half* As = (__half*)smraw;          // [2][BM][LDSH]
    __half* Bs = As + 2 * BM * LDSH;      // [2][BN][LDSH]

    const int tid = threadIdx.x, wid = tid >> 5, lane = tid & 31;
    const int warp_m = wid & 1;
    const int warp_n = wid >> 1;
    const int b = blockIdx.z;
    const int rowBase = blockIdx.y * BM;
    const int colBase = blockIdx.x * BN;
    const int tileX = blockIdx.x;
    const __half* Qb = d_qc + ((size_t)b * NN + rowBase) * KQK;
    const __half* Kb = d_kc + ((size_t)b * SS + colBase) * KQK;
    const uint32_t asb = smem_u32(As);
    const uint32_t bsb = smem_u32(Bs);

    float* Gt = G + ((size_t)b * NN + rowBase) * SS + colBase;
    float* At = A + ((size_t)b * NN + rowBase) * SS + colBase;

    float acc[4][4][4];
#pragma unroll
    for (int mt = 0; mt < 4; ++mt)
#pragma unroll
        for (int nt = 0; nt < 4; ++nt)
#pragma unroll
            for (int e = 0; e < 4; ++e) acc[mt][nt][e] = 0.0f;

#define ISSUE_STAGE(st, k0) do {                                              \
        _Pragma("unroll")                                                     \
        for (int l = 0; l < 4; ++l) {                                         \
            int idx = tid + l * 256;                                          \
            int row = idx >> 3;                                               \
            int c8  = (idx & 7) * 8;                                          \
            cp16(asb + (uint32_t)(((st) * BM * LDSH + row * LDSH + c8) * 2),  \
                 Qb + (size_t)row * KQK + (k0) + c8);                         \
            cp16(bsb + (uint32_t)(((st) * BN * LDSH + row * LDSH + c8) * 2),  \
                 Kb + (size_t)row * KQK + (k0) + c8);                         \
        }                                                                     \
        asm volatile("cp.async.commit_group;" ::: "memory");                  \
    } while (0)

    ISSUE_STAGE(0, 0);

    const int NK = KQK / BKH;   // 4
    for (int c = 0; c < NK; ++c) {
        if (c + 1 < NK) {
            ISSUE_STAGE((c + 1) & 1, (c + 1) * BKH);
            asm volatile("cp.async.wait_group 1;" ::: "memory");
        } else {
            asm volatile("cp.async.wait_group 0;" ::: "memory");
        }
        __syncthreads();

        // Interleaved zero-fill: 1/NK of this CTA's G/A tiles per chunk,
        // write-through stores drained under the MMA burst below.
#pragma unroll
        for (int l = 0; l < 4; ++l) {
            int f = tid + (c * 4 + l) * 256;   // 0..4095 float4 positions
            int row = f >> 5;                  // 32 float4 per 128-col row
            int c4 = (f & 31) * 4;
            stg_wt_zero16(Gt + (size_t)row * SS + c4);
            stg_wt_zero16(At + (size_t)row * SS + c4);
        }

        const int st = c & 1;
        const uint32_t ab = asb + (uint32_t)(st * BM * LDSH * 2);
        const uint32_t bbs = bsb + (uint32_t)(st * BN * LDSH * 2);

#pragma unroll
        for (int ks = 0; ks < BKH / 16; ++ks) {
            uint32_t a[4][4];
#pragma unroll
            for (int mt = 0; mt < 4; ++mt) {
                uint32_t addr = ab + (uint32_t)((((warp_m * 64 + mt * 16 + (lane & 15)) * LDSH)
                                 + ks * 16 + (lane >> 4) * 8) * 2);
                asm volatile(
                    "ldmatrix.sync.aligned.m8n8.x4.shared.b16 {%0,%1,%2,%3}, [%4];"
                    : "=r"(a[mt][0]), "=r"(a[mt][1]), "=r"(a[mt][2]), "=r"(a[mt][3])
                    : "r"(addr));
            }
            uint32_t bf[4][2];
#pragma unroll
            for (int g = 0; g < 2; ++g) {
                uint32_t addr = bbs + (uint32_t)((((warp_n * 32 + g * 16 + (lane & 15)) * LDSH)
                                 + ks * 16 + (lane >> 4) * 8) * 2);
                uint32_t r0, r1, r2, r3;
                asm volatile(
                    "ldmatrix.sync.aligned.m8n8.x4.shared.b16 {%0,%1,%2,%3}, [%4];"
                    : "=r"(r0), "=r"(r1), "=r"(r2), "=r"(r3)
                    : "r"(addr));
                bf[g * 2][0] = r0; bf[g * 2][1] = r2;
                bf[g * 2 + 1][0] = r1; bf[g * 2 + 1][1] = r3;
            }
#pragma unroll
            for (int mt = 0; mt < 4; ++mt)
#pragma unroll
                for (int nt = 0; nt < 4; ++nt) {
                    asm volatile(
                        "mma.sync.aligned.m16n8k16.row.col.f32.f16.f16.f32 "
                        "{%0,%1,%2,%3}, {%4,%5,%6,%7}, {%8,%9}, {%0,%1,%2,%3};"
                        : "+f"(acc[mt][nt][0]), "+f"(acc[mt][nt][1]),
                          "+f"(acc[mt][nt][2]), "+f"(acc[mt][nt][3])
                        : "r"(a[mt][0]), "r"(a[mt][1]), "r"(a[mt][2]), "r"(a[mt][3]),
                          "r"(bf[nt][0]), "r"(bf[nt][1]));
                }
        }
        __syncthreads();
    }
#undef ISSUE_STAGE

    // ---------------- Candidate-extraction epilogue --------------------
    float (*wmax)[4] = (float(*)[4])smraw;            // [128][4]
    float* tmax = (float*)(smraw + 128 * 4 * 4);      // [128]
    int*   scnt = (int*)(smraw + 128 * 4 * 4 + 512);  // [128]

#pragma unroll
    for (int mt = 0; mt < 4; ++mt) {
#pragma unroll
        for (int h = 0; h < 2; ++h) {
            float rm = -1e30f;
#pragma unroll
            for (int nt = 0; nt < 4; ++nt)
                rm = fmaxf(rm, fmaxf(acc[mt][nt][h * 2], acc[mt][nt][h * 2 + 1]));
            rm = fmaxf(rm, __shfl_xor_sync(0xffffffffu, rm, 1));
            rm = fmaxf(rm, __shfl_xor_sync(0xffffffffu, rm, 2));
            if ((lane & 3) == 0)
                wmax[warp_m * 64 + mt * 16 + h * 8 + (lane >> 2)][warp_n] = rm;
        }
    }
    __syncthreads();
    if (tid < 128) {
        float t = fmaxf(fmaxf(wmax[tid][0], wmax[tid][1]),
                        fmaxf(wmax[tid][2], wmax[tid][3]));
        tmax[tid] = t;
        scnt[tid] = 0;
    }
    __syncthreads();

    // Extract elements > tile_rowmax - 1 - MARGIN (superset under fp16 error)
#pragma unroll
    for (int mt = 0; mt < 4; ++mt) {
#pragma unroll
        for (int nt = 0; nt < 4; ++nt) {
#pragma unroll
            for (int e = 0; e < 4; ++e) {
                int r = warp_m * 64 + mt * 16 + ((e >> 1) ? 8 : 0) + (lane >> 2);
                float val = acc[mt][nt][e];
                if (val > tmax[r] - 1.0f - MARGIN) {
                    int pos = atomicAdd(&scnt[r], 1);
                    if (pos < NSLOT) {
                        size_t grow = (size_t)b * NN + rowBase + r;
                        size_t slot = (grow * NTILE + tileX) * NSLOT + pos;
                        d_cval[slot] = val;
                        d_cidx[slot] = colBase + warp_n * 32 + nt * 8
                                       + 2 * (lane & 3) + (e & 1);
                    }
                }
            }
        }
    }
    __syncthreads();
    if (tid < 128) {
        size_t grow = (size_t)b * NN + rowBase + tid;
        int cc = scnt[tid];
        d_ccnt[grow * NTILE + tileX] = cc < NSLOT ? cc : NSLOT;
    }
}

// ======= Fused exact-rescore + sparsemax + AV-gather + gate scatter ========
// One warp per row. Gate/A zeros were written by qk_hmma; only scatter here.
__global__ void __launch_bounds__(256) sparse_fused(
    const float* __restrict__ Q, const float* __restrict__ Kk,
    float* __restrict__ G, float* __restrict__ A,
    float* __restrict__ Vout, const float* __restrict__ Vals)
{
    __shared__ float cv[8][32];
    __shared__ int   ci[8][32];

    const int tid = threadIdx.x, wid = tid >> 5, lane = tid & 31;
    const int row = blockIdx.x * 8 + wid;       // 0..32767
    const int b = row >> 11;

    // Lanes 0..15 each own one tile's candidate list (approx values)
    int cnt = 0;
    float tv[NSLOT];
    int   tix[NSLOT];
    if (lane < NTILE) {
        cnt = d_ccnt[(size_t)row * NTILE + lane];
        const size_t base = ((size_t)row * NTILE + lane) * NSLOT;
#pragma unroll
        for (int s = 0; s < NSLOT; ++s) {
            if (s < cnt) { tv[s] = d_cval[base + s]; tix[s] = d_cidx[base + s]; }
        }
    }

    // Approx global row max
    float m = -1e30f;
#pragma unroll
    for (int s = 0; s < NSLOT; ++s)
        if (s < cnt) m = fmaxf(m, tv[s]);
#pragma unroll
    for (int o = 16; o > 0; o >>= 1) m = fmaxf(m, __shfl_xor_sync(0xffffffffu, m, o));
    const float thr = m - 1.0f - MARGIN;

    // Compact survivors (approx val > thr) into shared lists
    int base = 0;
#pragma unroll
    for (int s = 0; s < NSLOT; ++s) {
        bool p = (s < cnt) && (tv[s] > thr);
        unsigned msk = __ballot_sync(0xffffffffu, p);
        if (p) {
            int pos = base + __popc(msk & ((1u << lane) - 1u));
            if (pos < 32) { ci[wid][pos] = tix[s]; }
        }
        base += __popc(msk);
    }
    const int mc = base > 32 ? 32 : base;
    __syncwarp();

    // Exact fp32 rescoring of survivors: warp-cooperative dot products
    const float* Qr = Q + (size_t)row * DD;
    float4 q0 = ((const float4*)Qr)[lane * 2];
    float4 q1 = ((const float4*)Qr)[lane * 2 + 1];
    for (int i = 0; i < mc; ++i) {
        const float* Kr = Kk + ((size_t)b * SS + ci[wid][i]) * DD;
        float4 k0 = ((const float4*)Kr)[lane * 2];
        float4 k1 = ((const float4*)Kr)[lane * 2 + 1];
        float p = q0.x * k0.x + q0.y * k0.y + q0.z * k0.z + q0.w * k0.w
                + q1.x * k1.x + q1.y * k1.y + q1.z * k1.z + q1.w * k1.w;
#pragma unroll
        for (int o = 16; o > 0; o >>= 1) p += __shfl_xor_sync(0xffffffffu, p, o);
        cv[wid][i] = p;   // same value in all lanes
    }
    __syncwarp();

    // Sparsemax on exact candidate scores
    float cand = (lane < mc) ? cv[wid][lane] : -1e30f;
    float me = cand;
#pragma unroll
    for (int o = 16; o > 0; o >>= 1) me = fmaxf(me, __shfl_xor_sync(0xffffffffu, me, o));
    float lo = me - 1.0f, hi = me;
    for (int it = 0; it < 20; ++it) {
        float mid = 0.5f * (lo + hi);
        float s = fmaxf(cand - mid, 0.0f);
#pragma unroll
        for (int o = 16; o > 0; o >>= 1) s += __shfl_xor_sync(0xffffffffu, s, o);
        if (s >= 1.0f) lo = mid; else hi = mid;
    }
    float inz = (cand > lo) ? cand : 0.0f;
    float inc = (cand > lo) ? 1.0f : 0.0f;
#pragma unroll
    for (int o = 16; o > 0; o >>= 1) {
        inz += __shfl_xor_sync(0xffffffffu, inz, o);
        inc += __shfl_xor_sync(0xffffffffu, inc, o);
    }
    const float tau = (inz - 1.0f) / inc;
    const float g = fmaxf(cand - tau, 0.0f);

    // V[row,:] = sum_i g_i * Vals[b, s_i, :]
    float4 acc0 = make_float4(0.f, 0.f, 0.f, 0.f);
    float4 acc1 = make_float4(0.f, 0.f, 0.f, 0.f);
    for (int i = 0; i < mc; ++i) {
        float gi = __shfl_sync(0xffffffffu, g, i);
        if (gi > 0.0f) {
            const float4* vr = (const float4*)(Vals + ((size_t)b * SS + ci[wid][i]) * DD + lane * 8);
            float4 p0 = vr[0], p1 = vr[1];
            acc0.x += gi * p0.x; acc0.y += gi * p0.y; acc0.z += gi * p0.z; acc0.w += gi * p0.w;
            acc1.x += gi * p1.x; acc1.y += gi * p1.y; acc1.z += gi * p1.z; acc1.w += gi * p1.w;
        }
    }
    float4* vo = (float4*)(Vout + (size_t)row * DD + lane * 8);
    vo[0] = acc0; vo[1] = acc1;

    // Scatter nonzero gates (zeros pre-written by qk_hmma)
    if (lane < mc && g > 0.0f) {
        int s = ci[wid][lane];
        G[(size_t)row * SS + s] = g;
        A[(size_t)row * SS + s] = g;
    }
}

// ============================== launch =====================================
extern "C" void kernel_launch(void* const* d_in, const int* in_sizes, int n_in,
                              void* d_out, int out_size)
{
    const float* Q  = (const float*)d_in[0];
    const float* K  = (const float*)d_in[1];
    const float* Vv = (const float*)d_in[2];

    float* out  = (float*)d_out;
    float* Vout = out;
    float* Aout = out + (size_t)BB * NN * DD;
    float* Gout = Aout + (size_t)BB * NN * SS;

    const int QK_SMEM = 2 * (BM + BN) * LDSH * 2;     // 73,728 B
    cudaFuncSetAttribute(qk_hmma, cudaFuncAttributeMaxDynamicSharedMemorySize, QK_SMEM);

    // 1) convert Q,K to fp16 (hi only) into static scratch
    convert_kernel<<<(unsigned)((size_t)BB * NN * DD / 4 / 256), 256>>>(Q, K);

    // 2) approx scores via HMMA -> candidate lists; zero-fills G and A tiles
    dim3 g1(SS / BN, NN / BM, BB);
    qk_hmma<<<g1, 256, QK_SMEM>>>(Gout, Aout);

    // 3) exact rescore + sparsemax + AV gather + gate/A scatter
    sparse_fused<<<BB * NN / 8, 256>>>(Q, K, Gout, Aout, Vout, Vv);
}